// round 2
// baseline (speedup 1.0000x reference)
#include <cuda_runtime.h>
#include <cstdint>

#define N_NODES 100000
#define N_EDGES 1600000
#define D_IN    128
#define D_OUT   64

// Scratch (no allocation allowed in kernel_launch)
__device__ float g_xj[(size_t)N_NODES * D_OUT];
__device__ float g_a1[N_NODES];
__device__ float g_a2[N_NODES];
__device__ int   g_idx_is_i64;   // 1 if edge_index is int64, 0 if int32

// ---------------------------------------------------------------------------
// Kernel 0: detect edge_index dtype. For int64 data (all values < 2^31),
// odd 32-bit words are all zero; for int32 data they are random node ids.
// Deterministic for fixed inputs.
// ---------------------------------------------------------------------------
__global__ void sniff_kernel(const int* __restrict__ w) {
    int odd_zero = 1;
    for (int i = 1; i < 32; i += 2)
        if (w[i] != 0) odd_zero = 0;
    g_idx_is_i64 = odd_zero;
}

// ---------------------------------------------------------------------------
// Kernel 1: fused dual GEMM
//   out  = relu(x0 @ W1 + b1)   (x0_i, also serves as init of agg accumulator)
//   g_xj = relu(x0 @ W2 + b2)   (x0_j)
// Block: 256 threads, 32 rows per block. W1|W2 combined as a 128x128 tile in
// smem; x rows staged in smem with stride 129 (conflict-free).
// Each thread: 1 row x 16 contiguous output cols (cols 0..63 -> W1, 64..127 -> W2).
// ---------------------------------------------------------------------------
#define GEMM_TPB 256
#define GEMM_ROWS 32
#define GEMM_SMEM (128 * 128 * 4 + GEMM_ROWS * 129 * 4)

__global__ __launch_bounds__(GEMM_TPB) void gemm_kernel(
    const float* __restrict__ x0,
    const float* __restrict__ W1, const float* __restrict__ b1,
    const float* __restrict__ W2, const float* __restrict__ b2,
    float* __restrict__ out)
{
    extern __shared__ float sm[];
    float* sW = sm;                  // [128][128]: col<64 = W1, col>=64 = W2
    float* sx = sm + 128 * 128;      // [32][129]

    const int tid = threadIdx.x;

    // Load weights (combined layout)
    for (int i = tid; i < 128 * 64; i += GEMM_TPB) {
        int k = i >> 6, c = i & 63;
        sW[k * 128 + c]      = W1[i];
        sW[k * 128 + 64 + c] = W2[i];
    }

    // Load x tile (coalesced float4)
    const int row0 = blockIdx.x * GEMM_ROWS;
    const float4* x4 = (const float4*)(x0 + (size_t)row0 * D_IN);
    for (int i = tid; i < GEMM_ROWS * D_IN / 4; i += GEMM_TPB) {
        float4 v = x4[i];
        int r = (i * 4) / D_IN, c = (i * 4) % D_IN;
        float* p = sx + r * 129 + c;
        p[0] = v.x; p[1] = v.y; p[2] = v.z; p[3] = v.w;
    }
    __syncthreads();

    const int r  = tid & 31;        // local row
    const int cg = tid >> 5;        // 0..7 -> 16-col group within combined 128
    const int cbase = cg * 16;

    float acc[16];
#pragma unroll
    for (int j = 0; j < 16; j++) acc[j] = 0.f;

    const float* xrow = sx + r * 129;
#pragma unroll 8
    for (int k = 0; k < D_IN; k++) {
        float xv = xrow[k];
        const float4* wr = (const float4*)(sW + k * 128 + cbase);
#pragma unroll
        for (int j4 = 0; j4 < 4; j4++) {
            float4 w = wr[j4];
            acc[j4 * 4 + 0] += xv * w.x;
            acc[j4 * 4 + 1] += xv * w.y;
            acc[j4 * 4 + 2] += xv * w.z;
            acc[j4 * 4 + 3] += xv * w.w;
        }
    }

    const int row = row0 + r;
    if (cg < 4) {
        // x0_i -> d_out (acts as agg init)
        float* dst = out + (size_t)row * D_OUT + cbase;
#pragma unroll
        for (int j4 = 0; j4 < 4; j4++) {
            float4 v;
            v.x = fmaxf(acc[j4 * 4 + 0] + b1[cbase + j4 * 4 + 0], 0.f);
            v.y = fmaxf(acc[j4 * 4 + 1] + b1[cbase + j4 * 4 + 1], 0.f);
            v.z = fmaxf(acc[j4 * 4 + 2] + b1[cbase + j4 * 4 + 2], 0.f);
            v.w = fmaxf(acc[j4 * 4 + 3] + b1[cbase + j4 * 4 + 3], 0.f);
            ((float4*)dst)[j4] = v;
        }
    } else {
        const int cb = cbase - 64;
        float* dst = g_xj + (size_t)row * D_OUT + cb;
#pragma unroll
        for (int j4 = 0; j4 < 4; j4++) {
            float4 v;
            v.x = fmaxf(acc[j4 * 4 + 0] + b2[cb + j4 * 4 + 0], 0.f);
            v.y = fmaxf(acc[j4 * 4 + 1] + b2[cb + j4 * 4 + 1], 0.f);
            v.z = fmaxf(acc[j4 * 4 + 2] + b2[cb + j4 * 4 + 2], 0.f);
            v.w = fmaxf(acc[j4 * 4 + 3] + b2[cb + j4 * 4 + 3], 0.f);
            ((float4*)dst)[j4] = v;
        }
    }
}

// ---------------------------------------------------------------------------
// Kernel 2: a1 = x0_i @ wa1 + ba1 ; a2 = x0_j @ wa2 + ba2   (one warp per row)
// ---------------------------------------------------------------------------
__global__ __launch_bounds__(256) void att_kernel(
    const float* __restrict__ xi,
    const float* __restrict__ wa1, const float* __restrict__ ba1,
    const float* __restrict__ wa2, const float* __restrict__ ba2)
{
    const int w = (blockIdx.x * blockDim.x + threadIdx.x) >> 5;
    const int lane = threadIdx.x & 31;
    if (w >= N_NODES) return;

    const float* xirow = xi   + (size_t)w * D_OUT;
    const float* xjrow = g_xj + (size_t)w * D_OUT;

    float s1 = xirow[lane] * wa1[lane] + xirow[lane + 32] * wa1[lane + 32];
    float s2 = xjrow[lane] * wa2[lane] + xjrow[lane + 32] * wa2[lane + 32];
#pragma unroll
    for (int off = 16; off > 0; off >>= 1) {
        s1 += __shfl_down_sync(0xFFFFFFFFu, s1, off);
        s2 += __shfl_down_sync(0xFFFFFFFFu, s2, off);
    }
    if (lane == 0) {
        g_a1[w] = s1 + ba1[0];
        g_a2[w] = s2 + ba2[0];
    }
}

// ---------------------------------------------------------------------------
// Kernel 3: edge scatter.
//   att = sigmoid(a1[src] + a2[dst]); red.add out[src] += att * x0_j[dst]
// Half-warp per edge: 16 lanes x float4 gather + red.global.add.v4.f32.
// Handles both int64 and int32 edge_index via g_idx_is_i64.
// ---------------------------------------------------------------------------
__device__ __forceinline__ void red_add_v4(float* p, float4 v) {
    asm volatile("red.global.add.v4.f32 [%0], {%1,%2,%3,%4};"
                 :: "l"(__cvta_generic_to_global(p)),
                    "f"(v.x), "f"(v.y), "f"(v.z), "f"(v.w)
                 : "memory");
}

__global__ __launch_bounds__(256) void edge_kernel(
    const void* __restrict__ ei_raw,
    float* __restrict__ out)
{
    const int lane = threadIdx.x & 31;
    const int sub  = lane >> 4;        // half-warp id (0/1)
    const int l    = lane & 15;        // lane within half-warp
    const int warp = (blockIdx.x * blockDim.x + threadIdx.x) >> 5;
    const int nwarps = (gridDim.x * blockDim.x) >> 5;

    const int is64 = g_idx_is_i64;
    const long long* ei64 = (const long long*)ei_raw;
    const int*       ei32 = (const int*)ei_raw;

    for (int e2 = warp * 2; e2 < N_EDGES; e2 += nwarps * 2) {
        const int e = e2 + sub;
        if (e < N_EDGES) {
            int s, d;
            if (is64) {
                s = (int)ei64[e];
                d = (int)ei64[N_EDGES + e];
            } else {
                s = ei32[e];
                d = ei32[N_EDGES + e];
            }
            const float z = g_a1[s] + g_a2[d];
            const float att = 1.f / (1.f + __expf(-z));
            float4 v = *(const float4*)(g_xj + (size_t)d * D_OUT + l * 4);
            v.x *= att; v.y *= att; v.z *= att; v.w *= att;
            red_add_v4(out + (size_t)s * D_OUT + l * 4, v);
        }
    }
}

// ---------------------------------------------------------------------------
extern "C" void kernel_launch(void* const* d_in, const int* in_sizes, int n_in,
                              void* d_out, int out_size)
{
    const float*     x0  = (const float*)d_in[0];
    // d_in[1] = x1 (unused)
    const void*      ei  = d_in[2];
    const float*     W1  = (const float*)d_in[3];
    const float*     b1  = (const float*)d_in[4];
    const float*     W2  = (const float*)d_in[5];
    const float*     b2  = (const float*)d_in[6];
    const float*     wa1 = (const float*)d_in[7];
    const float*     ba1 = (const float*)d_in[8];
    const float*     wa2 = (const float*)d_in[9];
    const float*     ba2 = (const float*)d_in[10];
    float* out = (float*)d_out;

    cudaFuncSetAttribute(gemm_kernel,
                         cudaFuncAttributeMaxDynamicSharedMemorySize, GEMM_SMEM);

    // 0) detect edge_index dtype (int32 vs int64)
    sniff_kernel<<<1, 1>>>((const int*)ei);

    // 1) dual GEMM: writes x0_i into d_out, x0_j into g_xj
    gemm_kernel<<<N_NODES / GEMM_ROWS, GEMM_TPB, GEMM_SMEM>>>(
        x0, W1, b1, W2, b2, out);

    // 2) attention scalars
    att_kernel<<<(N_NODES * 32 + 255) / 256, 256>>>(out, wa1, ba1, wa2, ba2);

    // 3) edge scatter (red.add into d_out, already initialized to x0_i)
    edge_kernel<<<1184, 256>>>(ei, out);
}

// round 4
// speedup vs baseline: 1.3618x; 1.3618x over previous
#include <cuda_runtime.h>
#include <cstdint>

#define N_NODES 100000
#define N_EDGES 1600000
#define D_IN    128
#define D_OUT   64

// Scratch (no allocation allowed in kernel_launch)
__device__ float g_xj[(size_t)N_NODES * D_OUT];
__device__ float g_a1[N_NODES];
__device__ float g_a2[N_NODES];
__device__ int   g_idx_is_i64;   // 1 if edge_index is int64, 0 if int32

// ---------------------------------------------------------------------------
// Packed fp32 helpers (Blackwell FFMA2 path — ptxas only emits from PTX)
// ---------------------------------------------------------------------------
__device__ __forceinline__ void ffma2(unsigned long long& acc,
                                      unsigned long long ab,
                                      unsigned long long w) {
    asm("fma.rn.f32x2 %0, %1, %2, %0;" : "+l"(acc) : "l"(ab), "l"(w));
}
__device__ __forceinline__ unsigned long long pack2(float v) {
    unsigned long long r;
    asm("mov.b64 %0, {%1, %1};" : "=l"(r) : "f"(v));
    return r;
}
__device__ __forceinline__ float2 unpack2(unsigned long long v) {
    float2 u;
    asm("mov.b64 {%0, %1}, %2;" : "=f"(u.x), "=f"(u.y) : "l"(v));
    return u;
}

// ---------------------------------------------------------------------------
// Kernel 0: detect edge_index dtype (int64 vs int32). For int64 (< 2^31),
// all odd 32-bit words are zero. Deterministic for fixed inputs.
// ---------------------------------------------------------------------------
__global__ void sniff_kernel(const int* __restrict__ w) {
    int odd_zero = 1;
    for (int i = 1; i < 32; i += 2)
        if (w[i] != 0) odd_zero = 0;
    g_idx_is_i64 = odd_zero;
}

// ---------------------------------------------------------------------------
// Kernel 1: fused dual GEMM + attention scalars.
//   out  = relu(x0 @ W1 + b1)   (x0_i, also inits the agg accumulator)
//   g_xj = relu(x0 @ W2 + b2)   (x0_j)
//   g_a1 = x0_i @ wa1 + ba1 ; g_a2 = x0_j @ wa2 + ba2   (epilogue)
// 256 threads, 64 rows per block. W1|W2 combined 128x128 tile in smem.
// Each thread: 2 rows x 16 cols, accumulated in f32x2 pairs (FFMA2).
// Warp cg = tid>>5 selects the 16-col group (cg<4 -> W1 side, else W2 side).
// ---------------------------------------------------------------------------
#define GEMM_TPB  256
#define GEMM_ROWS 64
#define GEMM_SMEM (128 * 128 * 4 + GEMM_ROWS * 129 * 4)

__global__ __launch_bounds__(GEMM_TPB) void gemm_kernel(
    const float* __restrict__ x0,
    const float* __restrict__ W1, const float* __restrict__ b1,
    const float* __restrict__ W2, const float* __restrict__ b2,
    const float* __restrict__ wa1, const float* __restrict__ ba1,
    const float* __restrict__ wa2, const float* __restrict__ ba2,
    float* __restrict__ out)
{
    extern __shared__ float sm[];
    float* sW = sm;                   // [128][128]: col<64 = W1, col>=64 = W2
    float* sx = sm + 128 * 128;       // [64][129]
    // a-dot partials: [col-group 0..3][side][row]
    __shared__ float s_ap[4][2][GEMM_ROWS];

    const int tid = threadIdx.x;

    // Load weights (combined layout)
    for (int i = tid; i < 128 * 64; i += GEMM_TPB) {
        int k = i >> 6, c = i & 63;
        sW[k * 128 + c]      = W1[i];
        sW[k * 128 + 64 + c] = W2[i];
    }

    // Load x tile (coalesced float4), guard tail rows
    const int row0 = blockIdx.x * GEMM_ROWS;
    for (int i = tid; i < GEMM_ROWS * (D_IN / 4); i += GEMM_TPB) {
        int r = i >> 5;           // 32 float4 per row
        int c = (i & 31) * 4;
        int row = row0 + r;
        float4 v = make_float4(0.f, 0.f, 0.f, 0.f);
        if (row < N_NODES)
            v = *(const float4*)(x0 + (size_t)row * D_IN + c);
        float* p = sx + r * 129 + c;
        p[0] = v.x; p[1] = v.y; p[2] = v.z; p[3] = v.w;
    }
    __syncthreads();

    const int r     = tid & 31;     // local row (also r+32)
    const int cg    = tid >> 5;     // 16-col group within combined 128
    const int cbase = cg * 16;

    unsigned long long acc0[8], acc1[8];
#pragma unroll
    for (int p = 0; p < 8; p++) { acc0[p] = 0ull; acc1[p] = 0ull; }

    const float* xr0 = sx + r * 129;
    const float* xr1 = sx + (r + 32) * 129;

#pragma unroll 4
    for (int k = 0; k < D_IN; k++) {
        unsigned long long xx0 = pack2(xr0[k]);
        unsigned long long xx1 = pack2(xr1[k]);
        const ulonglong2* wr = (const ulonglong2*)(sW + k * 128 + cbase);
#pragma unroll
        for (int p4 = 0; p4 < 4; p4++) {
            ulonglong2 w = wr[p4];                 // 4 packed col-pairs
            ffma2(acc0[p4 * 2 + 0], xx0, w.x);
            ffma2(acc0[p4 * 2 + 1], xx0, w.y);
            ffma2(acc1[p4 * 2 + 0], xx1, w.x);
            ffma2(acc1[p4 * 2 + 1], xx1, w.y);
        }
    }

    // Epilogue: bias + relu + store + a-dot partials
    const bool  side1 = (cg < 4);             // true: W1/x0_i side
    const int   side  = side1 ? 0 : 1;
    const int   cgl   = cg & 3;               // col-group within side (0..3)
    const int   cb    = side1 ? cbase : (cbase - 64);
    const float* bias = side1 ? b1 : b2;
    const float* wa   = side1 ? wa1 : wa2;
    float* base = side1 ? out : g_xj;

#pragma unroll
    for (int half = 0; half < 2; half++) {
        const unsigned long long* acc = half ? acc1 : acc0;
        const int lr  = r + half * 32;
        const int row = row0 + lr;
        float partial = 0.f;
        if (row < N_NODES) {
            float v[16];
#pragma unroll
            for (int p = 0; p < 8; p++) {
                float2 u = unpack2(acc[p]);
                v[p * 2 + 0] = fmaxf(u.x + bias[cb + p * 2 + 0], 0.f);
                v[p * 2 + 1] = fmaxf(u.y + bias[cb + p * 2 + 1], 0.f);
                partial += v[p * 2 + 0] * wa[cb + p * 2 + 0];
                partial += v[p * 2 + 1] * wa[cb + p * 2 + 1];
            }
            float* dst = base + (size_t)row * D_OUT + cb;
#pragma unroll
            for (int p4 = 0; p4 < 4; p4++)
                ((float4*)dst)[p4] = make_float4(v[p4 * 4], v[p4 * 4 + 1],
                                                 v[p4 * 4 + 2], v[p4 * 4 + 3]);
        }
        s_ap[cgl][side][lr] = partial;   // each (cgl,side,lr) written by exactly 1 thread
    }
    __syncthreads();

    // Reduce 4 col-group partials per (side,row); 128 threads cover both sides.
    if (tid < 2 * GEMM_ROWS) {
        const int which = tid >> 6;       // 0 -> a1, 1 -> a2
        const int lr    = tid & 63;
        const int row   = row0 + lr;
        if (row < N_NODES) {
            float v = s_ap[0][which][lr] + s_ap[1][which][lr]
                    + s_ap[2][which][lr] + s_ap[3][which][lr]
                    + (which ? ba2[0] : ba1[0]);
            (which ? g_a2 : g_a1)[row] = v;
        }
    }
}

// ---------------------------------------------------------------------------
// Kernel 2: edge scatter.
//   att = sigmoid(a1[src] + a2[dst]); red.add out[src] += att * x0_j[dst]
// Half-warp per edge: 16 lanes x float4 gather + red.global.add.v4.f32.
// ---------------------------------------------------------------------------
__device__ __forceinline__ void red_add_v4(float* p, float4 v) {
    asm volatile("red.global.add.v4.f32 [%0], {%1,%2,%3,%4};"
                 :: "l"(__cvta_generic_to_global(p)),
                    "f"(v.x), "f"(v.y), "f"(v.z), "f"(v.w)
                 : "memory");
}

__global__ __launch_bounds__(256) void edge_kernel(
    const void* __restrict__ ei_raw,
    float* __restrict__ out)
{
    const int lane = threadIdx.x & 31;
    const int sub  = lane >> 4;        // half-warp id (0/1)
    const int l    = lane & 15;        // lane within half-warp
    const int warp = (blockIdx.x * blockDim.x + threadIdx.x) >> 5;
    const int nwarps = (gridDim.x * blockDim.x) >> 5;

    const int is64 = g_idx_is_i64;
    const long long* ei64 = (const long long*)ei_raw;
    const int*       ei32 = (const int*)ei_raw;

    for (int e2 = warp * 2; e2 < N_EDGES; e2 += nwarps * 2) {
        const int e = e2 + sub;
        if (e < N_EDGES) {
            int s, d;
            if (is64) {
                s = (int)__ldg(&ei64[e]);
                d = (int)__ldg(&ei64[N_EDGES + e]);
            } else {
                s = __ldg(&ei32[e]);
                d = __ldg(&ei32[N_EDGES + e]);
            }
            const float z = __ldg(&g_a1[s]) + __ldg(&g_a2[d]);
            const float att = 1.f / (1.f + __expf(-z));
            float4 v = __ldg((const float4*)(g_xj + (size_t)d * D_OUT + l * 4));
            v.x *= att; v.y *= att; v.z *= att; v.w *= att;
            red_add_v4(out + (size_t)s * D_OUT + l * 4, v);
        }
    }
}

// ---------------------------------------------------------------------------
extern "C" void kernel_launch(void* const* d_in, const int* in_sizes, int n_in,
                              void* d_out, int out_size)
{
    const float* x0  = (const float*)d_in[0];
    // d_in[1] = x1 (unused)
    const void*  ei  = d_in[2];
    const float* W1  = (const float*)d_in[3];
    const float* b1  = (const float*)d_in[4];
    const float* W2  = (const float*)d_in[5];
    const float* b2  = (const float*)d_in[6];
    const float* wa1 = (const float*)d_in[7];
    const float* ba1 = (const float*)d_in[8];
    const float* wa2 = (const float*)d_in[9];
    const float* ba2 = (const float*)d_in[10];
    float* out = (float*)d_out;

    cudaFuncSetAttribute(gemm_kernel,
                         cudaFuncAttributeMaxDynamicSharedMemorySize, GEMM_SMEM);

    // 0) detect edge_index dtype (int32 vs int64)
    sniff_kernel<<<1, 1>>>((const int*)ei);

    // 1) dual GEMM + att scalars: x0_i -> d_out, x0_j -> g_xj, a1/a2 -> globals
    gemm_kernel<<<(N_NODES + GEMM_ROWS - 1) / GEMM_ROWS, GEMM_TPB, GEMM_SMEM>>>(
        x0, W1, b1, W2, b2, wa1, ba1, wa2, ba2, out);

    // 2) edge scatter (red.add into d_out, already initialized to x0_i)
    edge_kernel<<<1184, 256>>>(ei, out);
}

// round 7
// speedup vs baseline: 1.4582x; 1.0708x over previous
#include <cuda_runtime.h>
#include <cuda_bf16.h>
#include <cstdint>

#define N_NODES 100000
#define N_EDGES 1600000
#define D_IN    128
#define D_OUT   64

// ---------------------------------------------------------------------------
// Scratch (no allocation allowed in kernel_launch)
// ---------------------------------------------------------------------------
__device__ float g_xj[(size_t)N_NODES * D_OUT];
__device__ float g_a1[N_NODES];
__device__ float g_a2[N_NODES];
__device__ int   g_idx_is_i64;          // 1 if edge_index is int64, 0 if int32
// Transposed combined weights, bf16 hi/lo split: [n=128][k=128]
__device__ uint4 g_Wthi4[128 * 128 * 2 / 16];
__device__ uint4 g_Wtlo4[128 * 128 * 2 / 16];

// ---------------------------------------------------------------------------
// PTX wrappers
// ---------------------------------------------------------------------------
__device__ __forceinline__ void ldsm_x4(uint32_t* r, uint32_t addr) {
    asm volatile("ldmatrix.sync.aligned.m8n8.x4.shared.b16 {%0,%1,%2,%3}, [%4];"
                 : "=r"(r[0]), "=r"(r[1]), "=r"(r[2]), "=r"(r[3]) : "r"(addr));
}
__device__ __forceinline__ void ldsm_x2(uint32_t* r, uint32_t addr) {
    asm volatile("ldmatrix.sync.aligned.m8n8.x2.shared.b16 {%0,%1}, [%2];"
                 : "=r"(r[0]), "=r"(r[1]) : "r"(addr));
}
__device__ __forceinline__ void mma_bf16(float* d, const uint32_t* a, const uint32_t* b) {
    asm volatile("mma.sync.aligned.m16n8k16.row.col.f32.bf16.bf16.f32 "
                 "{%0,%1,%2,%3}, {%4,%5,%6,%7}, {%8,%9}, {%0,%1,%2,%3};"
                 : "+f"(d[0]), "+f"(d[1]), "+f"(d[2]), "+f"(d[3])
                 : "r"(a[0]), "r"(a[1]), "r"(a[2]), "r"(a[3]),
                   "r"(b[0]), "r"(b[1]));
}

// ---------------------------------------------------------------------------
// Kernel 0 (prep): split combined transposed weights into bf16 hi/lo,
// and sniff edge_index dtype (int64 has all-zero odd 32-bit words).
//   Wt[n][k] = n<64 ? W1[k][n] : W2[k][n-64]
// ---------------------------------------------------------------------------
__global__ __launch_bounds__(256) void prep_kernel(
    const float* __restrict__ W1, const float* __restrict__ W2,
    const int* __restrict__ ei_words)
{
    const int idx = blockIdx.x * 256 + threadIdx.x;   // 64 blocks -> 16384
    const int n = idx >> 7, k = idx & 127;
    float w = (n < 64) ? W1[k * 64 + n] : W2[k * 64 + (n - 64)];
    __nv_bfloat16 hi = __float2bfloat16(w);
    __nv_bfloat16 lo = __float2bfloat16(w - __bfloat162float(hi));
    ((__nv_bfloat16*)g_Wthi4)[idx] = hi;
    ((__nv_bfloat16*)g_Wtlo4)[idx] = lo;

    if (blockIdx.x == 0 && threadIdx.x == 0) {
        int odd_zero = 1;
        for (int i = 1; i < 32; i += 2)
            if (ei_words[i] != 0) odd_zero = 0;
        g_idx_is_i64 = odd_zero;
    }
}

// ---------------------------------------------------------------------------
// Kernel 1: tensor-core dual GEMM (bf16 hi/lo split, fp32-accurate) + fused
// bias/relu/store + a1/a2 attention-scalar epilogue.
//   out  = relu(x0 @ W1 + b1)   (cols 0..63 of combined; inits agg)
//   g_xj = relu(x0 @ W2 + b2)   (cols 64..127)
//   g_a1/g_a2 = side @ wa + ba
// Block: 256 thr, 128 rows x 128 combined cols, K=128 resident in smem.
// Warp (of 8): wm=w>>1 -> rows wm*32..+31 ; wn=w&1 -> cols wn*64..+63.
// ---------------------------------------------------------------------------
#define GROWS 128
#define LDS_STRIDE 136                    // bf16 elems per row (272B, conflict-free)
#define TILE_BYTES (GROWS * LDS_STRIDE * 2)
#define GEMM_SMEM (4 * TILE_BYTES + 2 * 128 * 4)

__global__ __launch_bounds__(256) void gemm_kernel(
    const float* __restrict__ x0,
    const float* __restrict__ b1, const float* __restrict__ b2,
    const float* __restrict__ wa1, const float* __restrict__ ba1,
    const float* __restrict__ wa2, const float* __restrict__ ba2,
    float* __restrict__ out)
{
    extern __shared__ char smem[];
    __nv_bfloat16* sAhi = (__nv_bfloat16*)smem;
    __nv_bfloat16* sAlo = sAhi + GROWS * LDS_STRIDE;
    __nv_bfloat16* sBhi = sAlo + GROWS * LDS_STRIDE;
    __nv_bfloat16* sBlo = sBhi + GROWS * LDS_STRIDE;
    float* sBias = (float*)(sBlo + GROWS * LDS_STRIDE);
    float* sWa   = sBias + 128;

    const int tid  = threadIdx.x;
    const int row0 = blockIdx.x * GROWS;

    // Stage bias / wa (combined 128)
    if (tid < 128) {
        sBias[tid] = (tid < 64) ? b1[tid] : b2[tid - 64];
        sWa[tid]   = (tid < 64) ? wa1[tid] : wa2[tid - 64];
    }

    // Stage weights (already bf16 hi/lo, [n][k] layout), 16B chunks
    for (int i = tid; i < 2048; i += 256) {
        int n = i >> 4, k0 = (i & 15) * 8;
        *(uint4*)(sBhi + n * LDS_STRIDE + k0) = g_Wthi4[i];
        *(uint4*)(sBlo + n * LDS_STRIDE + k0) = g_Wtlo4[i];
    }

    // Stage x tile with on-the-fly hi/lo split (guard tail rows)
    for (int i = tid; i < GROWS * (D_IN / 4); i += 256) {
        int r = i >> 5, c = (i & 31) * 4;
        int row = row0 + r;
        float4 v = make_float4(0.f, 0.f, 0.f, 0.f);
        if (row < N_NODES)
            v = *(const float4*)(x0 + (size_t)row * D_IN + c);
        __nv_bfloat162 h01 = __floats2bfloat162_rn(v.x, v.y);
        __nv_bfloat162 h23 = __floats2bfloat162_rn(v.z, v.w);
        float2 f01 = __bfloat1622float2(h01);
        float2 f23 = __bfloat1622float2(h23);
        __nv_bfloat162 l01 = __floats2bfloat162_rn(v.x - f01.x, v.y - f01.y);
        __nv_bfloat162 l23 = __floats2bfloat162_rn(v.z - f23.x, v.w - f23.y);
        __nv_bfloat162* ph = (__nv_bfloat162*)(sAhi + r * LDS_STRIDE + c);
        __nv_bfloat162* pl = (__nv_bfloat162*)(sAlo + r * LDS_STRIDE + c);
        ph[0] = h01; ph[1] = h23;
        pl[0] = l01; pl[1] = l23;
    }
    __syncthreads();

    const int w    = tid >> 5;
    const int lane = tid & 31;
    const int m0   = (w >> 1) * 32;      // warp row base (local)
    const int wn   = w & 1;              // 0: W1/out side, 1: W2/g_xj side
    const int n0   = wn * 64;            // warp col base (combined)

    const uint32_t aAhi = (uint32_t)__cvta_generic_to_shared(sAhi);
    const uint32_t aAlo = (uint32_t)__cvta_generic_to_shared(sAlo);
    const uint32_t aBhi = (uint32_t)__cvta_generic_to_shared(sBhi);
    const uint32_t aBlo = (uint32_t)__cvta_generic_to_shared(sBlo);

    float acc[2][8][4];
#pragma unroll
    for (int mt = 0; mt < 2; mt++)
#pragma unroll
        for (int nt = 0; nt < 8; nt++)
#pragma unroll
            for (int q = 0; q < 4; q++) acc[mt][nt][q] = 0.f;

    // A-frag address: lanes 0-15 -> rows (lane&15) @k0 ; 16-31 -> same rows @k0+8
    const uint32_t a_row = m0 + (lane & 15);
    const uint32_t a_kof = (lane >> 4) * 8;
    // B-frag address (x2): lanes 0-7 -> rows n+(lane&7) @k0 ; 8-15 -> @k0+8
    const uint32_t b_row = n0 + (lane & 7);
    const uint32_t b_kof = ((lane >> 3) & 1) * 8;

#pragma unroll
    for (int kk = 0; kk < 8; kk++) {
        const uint32_t k0 = kk * 16;
        uint32_t ahi[2][4], alo[2][4];
#pragma unroll
        for (int mt = 0; mt < 2; mt++) {
            uint32_t off = ((a_row + mt * 16) * LDS_STRIDE + k0 + a_kof) * 2;
            ldsm_x4(ahi[mt], aAhi + off);
            ldsm_x4(alo[mt], aAlo + off);
        }
#pragma unroll
        for (int nt = 0; nt < 8; nt++) {
            uint32_t off = ((b_row + nt * 8) * LDS_STRIDE + k0 + b_kof) * 2;
            uint32_t bhi[2], blo[2];
            ldsm_x2(bhi, aBhi + off);
            ldsm_x2(blo, aBlo + off);
#pragma unroll
            for (int mt = 0; mt < 2; mt++) {
                mma_bf16(acc[mt][nt], ahi[mt], bhi);
                mma_bf16(acc[mt][nt], ahi[mt], blo);
                mma_bf16(acc[mt][nt], alo[mt], bhi);
            }
        }
    }

    // Epilogue: bias + relu + store + per-row attention partials
    float* basep = wn ? g_xj : out;
    const float ba = __ldg(wn ? ba2 : ba1);
    float p[2][2] = {{0.f, 0.f}, {0.f, 0.f}};

#pragma unroll
    for (int mt = 0; mt < 2; mt++) {
        const int rA = row0 + m0 + mt * 16 + (lane >> 2);   // rows rA, rA+8
#pragma unroll
        for (int nt = 0; nt < 8; nt++) {
            const int cg = n0 + nt * 8 + (lane & 3) * 2;    // combined col
            const int cs = cg - n0;                          // col within side
            const float bb0 = sBias[cg],  bb1 = sBias[cg + 1];
            const float wv0 = sWa[cg],    wv1 = sWa[cg + 1];
            float v0 = fmaxf(acc[mt][nt][0] + bb0, 0.f);
            float v1 = fmaxf(acc[mt][nt][1] + bb1, 0.f);
            float v2 = fmaxf(acc[mt][nt][2] + bb0, 0.f);
            float v3 = fmaxf(acc[mt][nt][3] + bb1, 0.f);
            if (rA < N_NODES)
                *(float2*)(basep + (size_t)rA * D_OUT + cs) = make_float2(v0, v1);
            if (rA + 8 < N_NODES)
                *(float2*)(basep + (size_t)(rA + 8) * D_OUT + cs) = make_float2(v2, v3);
            p[mt][0] += v0 * wv0 + v1 * wv1;
            p[mt][1] += v2 * wv0 + v3 * wv1;
        }
    }

    // Quad reduce (lanes sharing a row are lane^1, lane^2) and write a1/a2
    float* ga = wn ? g_a2 : g_a1;
#pragma unroll
    for (int mt = 0; mt < 2; mt++)
#pragma unroll
        for (int h = 0; h < 2; h++) {
            float s = p[mt][h];
            s += __shfl_xor_sync(0xFFFFFFFFu, s, 1);
            s += __shfl_xor_sync(0xFFFFFFFFu, s, 2);
            const int row = row0 + m0 + mt * 16 + h * 8 + (lane >> 2);
            if ((lane & 3) == 0 && row < N_NODES)
                ga[row] = s + ba;
        }
}

// ---------------------------------------------------------------------------
// Kernel 2: edge scatter (unchanged, known-good).
//   att = sigmoid(a1[src] + a2[dst]); red.add out[src] += att * x0_j[dst]
// ---------------------------------------------------------------------------
__device__ __forceinline__ void red_add_v4(float* p, float4 v) {
    asm volatile("red.global.add.v4.f32 [%0], {%1,%2,%3,%4};"
                 :: "l"(__cvta_generic_to_global(p)),
                    "f"(v.x), "f"(v.y), "f"(v.z), "f"(v.w)
                 : "memory");
}

__global__ __launch_bounds__(256) void edge_kernel(
    const void* __restrict__ ei_raw,
    float* __restrict__ out)
{
    const int lane = threadIdx.x & 31;
    const int sub  = lane >> 4;
    const int l    = lane & 15;
    const int warp = (blockIdx.x * blockDim.x + threadIdx.x) >> 5;
    const int nwarps = (gridDim.x * blockDim.x) >> 5;

    const int is64 = g_idx_is_i64;
    const long long* ei64 = (const long long*)ei_raw;
    const int*       ei32 = (const int*)ei_raw;

    for (int e2 = warp * 2; e2 < N_EDGES; e2 += nwarps * 2) {
        const int e = e2 + sub;
        if (e < N_EDGES) {
            int s, d;
            if (is64) {
                s = (int)__ldg(&ei64[e]);
                d = (int)__ldg(&ei64[N_EDGES + e]);
            } else {
                s = __ldg(&ei32[e]);
                d = __ldg(&ei32[N_EDGES + e]);
            }
            const float z = __ldg(&g_a1[s]) + __ldg(&g_a2[d]);
            const float att = 1.f / (1.f + __expf(-z));
            float4 v = __ldg((const float4*)(g_xj + (size_t)d * D_OUT + l * 4));
            v.x *= att; v.y *= att; v.z *= att; v.w *= att;
            red_add_v4(out + (size_t)s * D_OUT + l * 4, v);
        }
    }
}

// ---------------------------------------------------------------------------
extern "C" void kernel_launch(void* const* d_in, const int* in_sizes, int n_in,
                              void* d_out, int out_size)
{
    const float* x0  = (const float*)d_in[0];
    // d_in[1] = x1 (unused)
    const void*  ei  = d_in[2];
    const float* W1  = (const float*)d_in[3];
    const float* b1  = (const float*)d_in[4];
    const float* W2  = (const float*)d_in[5];
    const float* b2  = (const float*)d_in[6];
    const float* wa1 = (const float*)d_in[7];
    const float* ba1 = (const float*)d_in[8];
    const float* wa2 = (const float*)d_in[9];
    const float* ba2 = (const float*)d_in[10];
    float* out = (float*)d_out;

    cudaFuncSetAttribute(gemm_kernel,
                         cudaFuncAttributeMaxDynamicSharedMemorySize, GEMM_SMEM);

    // 0) weight split (bf16 hi/lo, transposed) + edge-index dtype sniff
    prep_kernel<<<64, 256>>>(W1, W2, (const int*)ei);

    // 1) tensor-core dual GEMM + att scalars
    gemm_kernel<<<(N_NODES + GROWS - 1) / GROWS, 256, GEMM_SMEM>>>(
        x0, b1, b2, wa1, ba1, wa2, ba2, out);

    // 2) edge scatter (red.add into d_out, already initialized to x0_i)
    edge_kernel<<<1184, 256>>>(ei, out);
}

// round 10
// speedup vs baseline: 1.5937x; 1.0929x over previous
#include <cuda_runtime.h>
#include <cuda_bf16.h>
#include <cstdint>

#define N_NODES 100000
#define N_EDGES 1600000
#define D_IN    128
#define D_OUT   64

// ---------------------------------------------------------------------------
// Scratch (no allocation allowed in kernel_launch)
// ---------------------------------------------------------------------------
__device__ float g_xj[(size_t)N_NODES * D_OUT];
__device__ float g_a1[N_NODES];
__device__ float g_a2[N_NODES];
__device__ int   g_idx_is_i64;          // 1 if edge_index is int64, 0 if int32
// Transposed combined weights, bf16 hi/lo split: [n=128][k=128]
__device__ uint4 g_Wthi4[128 * 128 * 2 / 16];
__device__ uint4 g_Wtlo4[128 * 128 * 2 / 16];

// ---------------------------------------------------------------------------
// PTX wrappers
// ---------------------------------------------------------------------------
__device__ __forceinline__ void ldsm_x4(uint32_t* r, uint32_t addr) {
    asm volatile("ldmatrix.sync.aligned.m8n8.x4.shared.b16 {%0,%1,%2,%3}, [%4];"
                 : "=r"(r[0]), "=r"(r[1]), "=r"(r[2]), "=r"(r[3]) : "r"(addr));
}
__device__ __forceinline__ void mma_bf16(float* d, const uint32_t* a, const uint32_t* b) {
    asm volatile("mma.sync.aligned.m16n8k16.row.col.f32.bf16.bf16.f32 "
                 "{%0,%1,%2,%3}, {%4,%5,%6,%7}, {%8,%9}, {%0,%1,%2,%3};"
                 : "+f"(d[0]), "+f"(d[1]), "+f"(d[2]), "+f"(d[3])
                 : "r"(a[0]), "r"(a[1]), "r"(a[2]), "r"(a[3]),
                   "r"(b[0]), "r"(b[1]));
}

// ---------------------------------------------------------------------------
// Kernel 0 (prep): split combined transposed weights into bf16 hi/lo,
// and sniff edge_index dtype (int64 has all-zero odd 32-bit words).
//   Wt[n][k] = n<64 ? W1[k][n] : W2[k][n-64]
// ---------------------------------------------------------------------------
__global__ __launch_bounds__(256) void prep_kernel(
    const float* __restrict__ W1, const float* __restrict__ W2,
    const int* __restrict__ ei_words)
{
    const int idx = blockIdx.x * 256 + threadIdx.x;   // 64 blocks -> 16384
    const int n = idx >> 7, k = idx & 127;
    float w = (n < 64) ? W1[k * 64 + n] : W2[k * 64 + (n - 64)];
    __nv_bfloat16 hi = __float2bfloat16(w);
    __nv_bfloat16 lo = __float2bfloat16(w - __bfloat162float(hi));
    ((__nv_bfloat16*)g_Wthi4)[idx] = hi;
    ((__nv_bfloat16*)g_Wtlo4)[idx] = lo;

    if (blockIdx.x == 0 && threadIdx.x == 0) {
        int odd_zero = 1;
        for (int i = 1; i < 32; i += 2)
            if (ei_words[i] != 0) odd_zero = 0;
        g_idx_is_i64 = odd_zero;
    }
}

// ---------------------------------------------------------------------------
// Kernel 1: tensor-core dual GEMM (bf16 hi/lo split, fp32-accurate) + fused
// bias/relu/store + a1/a2 attention-scalar epilogue.
// Block: 256 thr, 64 rows x 128 combined cols, K=128 resident in smem.
// smem ~105.5 KB -> 2 CTAs/SM (16 warps) for latency hiding.
// Warp (of 8): rows (w>>1)*16..+15 ; cols (w&1)*64..+63 (w&1: 0=W1/out, 1=W2/xj)
// ---------------------------------------------------------------------------
#define GROWS 64
#define LDS_STRIDE 136                    // bf16 elems per row (272B, conflict-free)
#define A_TILE (GROWS * LDS_STRIDE)       // elems
#define B_TILE (128 * LDS_STRIDE)
#define GEMM_SMEM ((2 * A_TILE + 2 * B_TILE) * 2 + 2 * 128 * 4)

__global__ __launch_bounds__(256) void gemm_kernel(
    const float* __restrict__ x0,
    const float* __restrict__ b1, const float* __restrict__ b2,
    const float* __restrict__ wa1, const float* __restrict__ ba1,
    const float* __restrict__ wa2, const float* __restrict__ ba2,
    float* __restrict__ out)
{
    extern __shared__ char smem[];
    __nv_bfloat16* sAhi = (__nv_bfloat16*)smem;
    __nv_bfloat16* sAlo = sAhi + A_TILE;
    __nv_bfloat16* sBhi = sAlo + A_TILE;
    __nv_bfloat16* sBlo = sBhi + B_TILE;
    float* sBias = (float*)(sBlo + B_TILE);
    float* sWa   = sBias + 128;

    const int tid  = threadIdx.x;
    const int row0 = blockIdx.x * GROWS;

    // Stage bias / wa (combined 128)
    if (tid < 128) {
        sBias[tid] = (tid < 64) ? b1[tid] : b2[tid - 64];
        sWa[tid]   = (tid < 64) ? wa1[tid] : wa2[tid - 64];
    }

    // Stage weights (already bf16 hi/lo, [n][k] layout), 16B chunks
    for (int i = tid; i < 2048; i += 256) {
        int n = i >> 4, k0 = (i & 15) * 8;
        *(uint4*)(sBhi + n * LDS_STRIDE + k0) = g_Wthi4[i];
        *(uint4*)(sBlo + n * LDS_STRIDE + k0) = g_Wtlo4[i];
    }

    // Stage x tile with on-the-fly hi/lo split (guard tail rows)
    for (int i = tid; i < GROWS * (D_IN / 4); i += 256) {
        int r = i >> 5, c = (i & 31) * 4;
        int row = row0 + r;
        float4 v = make_float4(0.f, 0.f, 0.f, 0.f);
        if (row < N_NODES)
            v = *(const float4*)(x0 + (size_t)row * D_IN + c);
        __nv_bfloat162 h01 = __floats2bfloat162_rn(v.x, v.y);
        __nv_bfloat162 h23 = __floats2bfloat162_rn(v.z, v.w);
        float2 f01 = __bfloat1622float2(h01);
        float2 f23 = __bfloat1622float2(h23);
        __nv_bfloat162 l01 = __floats2bfloat162_rn(v.x - f01.x, v.y - f01.y);
        __nv_bfloat162 l23 = __floats2bfloat162_rn(v.z - f23.x, v.w - f23.y);
        __nv_bfloat162* ph = (__nv_bfloat162*)(sAhi + r * LDS_STRIDE + c);
        __nv_bfloat162* pl = (__nv_bfloat162*)(sAlo + r * LDS_STRIDE + c);
        ph[0] = h01; ph[1] = h23;
        pl[0] = l01; pl[1] = l23;
    }
    __syncthreads();

    const int w    = tid >> 5;
    const int lane = tid & 31;
    const int m0   = (w >> 1) * 16;      // warp row base (local), 16 rows
    const int wn   = w & 1;              // 0: W1/out side, 1: W2/g_xj side
    const int n0   = wn * 64;            // warp col base (combined)

    const uint32_t aAhi = (uint32_t)__cvta_generic_to_shared(sAhi);
    const uint32_t aAlo = (uint32_t)__cvta_generic_to_shared(sAlo);
    const uint32_t aBhi = (uint32_t)__cvta_generic_to_shared(sBhi);
    const uint32_t aBlo = (uint32_t)__cvta_generic_to_shared(sBlo);

    float acc[8][4];
#pragma unroll
    for (int nt = 0; nt < 8; nt++)
#pragma unroll
        for (int q = 0; q < 4; q++) acc[nt][q] = 0.f;

    // A x4 frag address: lanes 0-15 -> rows m0+(lane&15)@k0; 16-31 -> @k0+8
    const uint32_t a_row = m0 + (lane & 15);
    const uint32_t a_kof = (lane >> 4) * 8;
    // B x4 spanning 2 n-tiles: mats = {rows n..n+7@k0, @k0+8, rows n+8..n+15@k0, @k0+8}
    const uint32_t b_row = (lane & 7) + ((lane >> 4) << 3);   // + ntp*16 + n0
    const uint32_t b_kof = ((lane >> 3) & 1) * 8;

#pragma unroll
    for (int kk = 0; kk < 8; kk++) {
        const uint32_t k0 = kk * 16;
        uint32_t ahi[4], alo[4];
        {
            uint32_t off = (a_row * LDS_STRIDE + k0 + a_kof) * 2;
            ldsm_x4(ahi, aAhi + off);
            ldsm_x4(alo, aAlo + off);
        }
#pragma unroll
        for (int ntp = 0; ntp < 4; ntp++) {
            uint32_t off = ((n0 + ntp * 16 + b_row) * LDS_STRIDE + k0 + b_kof) * 2;
            uint32_t bhi[4], blo[4];
            ldsm_x4(bhi, aBhi + off);
            ldsm_x4(blo, aBlo + off);
            // bhi[0..1] -> n-tile 2*ntp ; bhi[2..3] -> n-tile 2*ntp+1
            mma_bf16(acc[ntp * 2 + 0], ahi, bhi + 0);
            mma_bf16(acc[ntp * 2 + 0], ahi, blo + 0);
            mma_bf16(acc[ntp * 2 + 0], alo, bhi + 0);
            mma_bf16(acc[ntp * 2 + 1], ahi, bhi + 2);
            mma_bf16(acc[ntp * 2 + 1], ahi, blo + 2);
            mma_bf16(acc[ntp * 2 + 1], alo, bhi + 2);
        }
    }

    // Epilogue: bias + relu + store + per-row attention partials
    float* basep = wn ? g_xj : out;
    const float ba = __ldg(wn ? ba2 : ba1);
    float p0 = 0.f, p1 = 0.f;          // partials for rows rA, rA+8
    const int rA = row0 + m0 + (lane >> 2);

#pragma unroll
    for (int nt = 0; nt < 8; nt++) {
        const int cg = n0 + nt * 8 + (lane & 3) * 2;    // combined col
        const int cs = cg - n0;                          // col within side
        const float bb0 = sBias[cg],  bb1 = sBias[cg + 1];
        const float wv0 = sWa[cg],    wv1 = sWa[cg + 1];
        float v0 = fmaxf(acc[nt][0] + bb0, 0.f);
        float v1 = fmaxf(acc[nt][1] + bb1, 0.f);
        float v2 = fmaxf(acc[nt][2] + bb0, 0.f);
        float v3 = fmaxf(acc[nt][3] + bb1, 0.f);
        if (rA < N_NODES)
            *(float2*)(basep + (size_t)rA * D_OUT + cs) = make_float2(v0, v1);
        if (rA + 8 < N_NODES)
            *(float2*)(basep + (size_t)(rA + 8) * D_OUT + cs) = make_float2(v2, v3);
        p0 += v0 * wv0 + v1 * wv1;
        p1 += v2 * wv0 + v3 * wv1;
    }

    // Quad reduce (lanes sharing a row are lane^1, lane^2) and write a1/a2
    float* ga = wn ? g_a2 : g_a1;
#pragma unroll
    for (int h = 0; h < 2; h++) {
        float s = h ? p1 : p0;
        s += __shfl_xor_sync(0xFFFFFFFFu, s, 1);
        s += __shfl_xor_sync(0xFFFFFFFFu, s, 2);
        const int row = row0 + m0 + h * 8 + (lane >> 2);
        if ((lane & 3) == 0 && row < N_NODES)
            ga[row] = s + ba;
    }
}

// ---------------------------------------------------------------------------
// Kernel 2: edge scatter with 2-edge ILP per half-warp.
//   att = sigmoid(a1[src] + a2[dst]); red.add out[src] += att * x0_j[dst]
// 4 edges per warp per iteration: batched idx/a/gather loads before the reds.
// ---------------------------------------------------------------------------
__device__ __forceinline__ void red_add_v4(float* p, float4 v) {
    asm volatile("red.global.add.v4.f32 [%0], {%1,%2,%3,%4};"
                 :: "l"(__cvta_generic_to_global(p)),
                    "f"(v.x), "f"(v.y), "f"(v.z), "f"(v.w)
                 : "memory");
}

__global__ __launch_bounds__(256) void edge_kernel(
    const void* __restrict__ ei_raw,
    float* __restrict__ out)
{
    const int lane = threadIdx.x & 31;
    const int sub  = lane >> 4;        // half-warp id (0/1)
    const int l    = lane & 15;        // lane within half-warp
    const int warp = (blockIdx.x * blockDim.x + threadIdx.x) >> 5;
    const int nwarps = (gridDim.x * blockDim.x) >> 5;

    const int is64 = g_idx_is_i64;
    const long long* ei64 = (const long long*)ei_raw;
    const int*       ei32 = (const int*)ei_raw;

    for (int e4 = warp * 4; e4 < N_EDGES; e4 += nwarps * 4) {
        const int e0 = e4 + sub * 2;
        const int e1 = e0 + 1;
        const bool ok0 = e0 < N_EDGES;
        const bool ok1 = e1 < N_EDGES;

        int s0 = 0, d0 = 0, s1 = 0, d1 = 0;
        if (is64) {
            if (ok0) { s0 = (int)__ldg(&ei64[e0]); d0 = (int)__ldg(&ei64[N_EDGES + e0]); }
            if (ok1) { s1 = (int)__ldg(&ei64[e1]); d1 = (int)__ldg(&ei64[N_EDGES + e1]); }
        } else {
            if (ok0) { s0 = __ldg(&ei32[e0]); d0 = __ldg(&ei32[N_EDGES + e0]); }
            if (ok1) { s1 = __ldg(&ei32[e1]); d1 = __ldg(&ei32[N_EDGES + e1]); }
        }

        const float z0 = __ldg(&g_a1[s0]) + __ldg(&g_a2[d0]);
        const float z1 = __ldg(&g_a1[s1]) + __ldg(&g_a2[d1]);
        float4 u0 = __ldg((const float4*)(g_xj + (size_t)d0 * D_OUT + l * 4));
        float4 u1 = __ldg((const float4*)(g_xj + (size_t)d1 * D_OUT + l * 4));
        const float att0 = 1.f / (1.f + __expf(-z0));
        const float att1 = 1.f / (1.f + __expf(-z1));
        u0.x *= att0; u0.y *= att0; u0.z *= att0; u0.w *= att0;
        u1.x *= att1; u1.y *= att1; u1.z *= att1; u1.w *= att1;

        if (ok0) red_add_v4(out + (size_t)s0 * D_OUT + l * 4, u0);
        if (ok1) red_add_v4(out + (size_t)s1 * D_OUT + l * 4, u1);
    }
}

// ---------------------------------------------------------------------------
extern "C" void kernel_launch(void* const* d_in, const int* in_sizes, int n_in,
                              void* d_out, int out_size)
{
    const float* x0  = (const float*)d_in[0];
    // d_in[1] = x1 (unused)
    const void*  ei  = d_in[2];
    const float* W1  = (const float*)d_in[3];
    const float* b1  = (const float*)d_in[4];
    const float* W2  = (const float*)d_in[5];
    const float* b2  = (const float*)d_in[6];
    const float* wa1 = (const float*)d_in[7];
    const float* ba1 = (const float*)d_in[8];
    const float* wa2 = (const float*)d_in[9];
    const float* ba2 = (const float*)d_in[10];
    float* out = (float*)d_out;

    cudaFuncSetAttribute(gemm_kernel,
                         cudaFuncAttributeMaxDynamicSharedMemorySize, GEMM_SMEM);

    // 0) weight split (bf16 hi/lo, transposed) + edge-index dtype sniff
    prep_kernel<<<64, 256>>>(W1, W2, (const int*)ei);

    // 1) tensor-core dual GEMM + att scalars
    gemm_kernel<<<(N_NODES + GROWS - 1) / GROWS, 256, GEMM_SMEM>>>(
        x0, b1, b2, wa1, ba1, wa2, ba2, out);

    // 2) edge scatter (red.add into d_out, already initialized to x0_i)
    edge_kernel<<<1184, 256>>>(ei, out);
}